// round 11
// baseline (speedup 1.0000x reference)
#include <cuda_runtime.h>
#include <cstdint>

#define THRESH 1.25f

constexpr int B    = 16;
constexpr int CIN  = 8192;   // 64*64*2
constexpr int CHID = 512;
constexpr int COUT = 100;
constexpr int T    = 300;
constexpr int NW0  = CIN / 32;   // 256 words per (b,t)
constexpr int NW1  = CHID / 32;  // 16 words per (b,t)
constexpr int HW   = NW0 / 2;    // 128 words per half
constexpr int G    = 10;         // t-group size for layers 2/3 (300 = 30*10)
constexpr int NTG  = T / G;      // 30 groups

// ---------------- scratch (static device globals; allocation-free) -------------
__device__ __align__(256) float    d_WT1[CIN * CHID];     // 16 MB  [i][o]
__device__ __align__(256) float    d_WT2[CHID * CHID];    // 1 MB   [i][o]
__device__ __align__(256) float    d_WT3[CHID * 128];     // 256 KB [i][o pad 128]
__device__ __align__(256) float    d_scale1[CHID];
__device__ __align__(256) unsigned d_bits0[T * B * NW0];  // input spikes [t][b][w]
__device__ __align__(256) unsigned d_bits1[T * B * NW1];  // hidden spikes [t][b][w]
__device__ __align__(256) unsigned d_bits2[T * B * NW1];
__device__ __align__(256) float    d_zpart[2][T * B * CHID]; // layer-1 i-half partials
__device__ __align__(256) float    d_z [T * B * CHID];    // layer-2 z [t][b][o]
__device__ __align__(256) float    d_z3[T * B * COUT];

// ---------------- fused: bitpack (blocks 0..4095) + layer-1 row norms ----------
__global__ __launch_bounds__(256) void bitpack_norm0(const float* __restrict__ spike,
                                                     const float* __restrict__ v1,
                                                     const float* __restrict__ g1)
{
    __shared__ unsigned char sb[32 * 308];
    __shared__ float red[8];
    int blk = blockIdx.x;
    int tid = threadIdx.x, lane = tid & 31, w = tid >> 5;

    if (blk < 4096) {
        int b  = blk >> 8;
        int ig = blk & 255;
        #pragma unroll
        for (int k = 0; k < 4; k++) {
            int il = w + 8 * k;
            const float4* row4 = (const float4*)(spike + ((size_t)b * CIN + ig * 32 + il) * T);
            #pragma unroll
            for (int j = 0; j < 3; j++) {
                int f = lane + 32 * j;
                if (f < 75) {
                    float4 v = row4[f];
                    unsigned p = (v.x > 0.5f ? 1u : 0u)
                               | (v.y > 0.5f ? 1u : 0u) << 8
                               | (v.z > 0.5f ? 1u : 0u) << 16
                               | (v.w > 0.5f ? 1u : 0u) << 24;
                    *(unsigned*)&sb[il * 308 + 4 * f] = p;
                }
            }
        }
        __syncthreads();
        for (int t = tid; t < T; t += 256) {
            unsigned m = 0;
            #pragma unroll
            for (int i = 0; i < 32; i++) m |= (unsigned)sb[i * 308 + t] << i;
            d_bits0[(size_t)t * (B * NW0) + b * NW0 + ig] = m;
        }
    } else {
        int r = blk - 4096;   // 0..511
        const float* row = v1 + (size_t)r * CIN;
        float s = 0.f;
        for (int i = tid; i < CIN; i += 256) { float x = row[i]; s = fmaf(x, x, s); }
        #pragma unroll
        for (int d = 16; d > 0; d >>= 1) s += __shfl_down_sync(0xffffffffu, s, d);
        if (lane == 0) red[w] = s;
        __syncthreads();
        if (tid == 0) {
            float tot = 0.f;
            #pragma unroll
            for (int j = 0; j < 8; j++) tot += red[j];
            d_scale1[r] = g1[r] / sqrtf(tot);
        }
    }
}

// ---------------- layer-1 transpose + scale: WT1[i][o] = v1[o][i]*scale1[o] ----
__global__ void wnorm_t0(const float* __restrict__ v)
{
    __shared__ float tile[64][65];
    int i0 = blockIdx.x * 64, o0 = blockIdx.y * 64;
    int tid = threadIdx.x;
    int oy = tid >> 4;
    int ix = (tid & 15) * 4;

    #pragma unroll
    for (int k = 0; k < 4; k++) {
        int ol = oy + k * 16;
        float4 val = *(const float4*)&v[(size_t)(o0 + ol) * CIN + i0 + ix];
        tile[ix + 0][ol] = val.x;
        tile[ix + 1][ol] = val.y;
        tile[ix + 2][ol] = val.z;
        tile[ix + 3][ol] = val.w;
    }
    __syncthreads();

    int iy = tid >> 4;
    int ox = (tid & 15) * 4;
    float4 sc = *(const float4*)&d_scale1[o0 + ox];
    #pragma unroll
    for (int k = 0; k < 4; k++) {
        int il = iy + k * 16;
        float4 w;
        w.x = tile[il][ox + 0] * sc.x;
        w.y = tile[il][ox + 1] * sc.y;
        w.z = tile[il][ox + 2] * sc.z;
        w.w = tile[il][ox + 3] * sc.w;
        *(float4*)&d_WT1[(size_t)(i0 + il) * CHID + o0 + ox] = w;
    }
}

// ---------------- fused prep for layers 2+3: norms + transpose ------------------
__global__ __launch_bounds__(256) void fused_prep23(const float* __restrict__ v2,
                                                    const float* __restrict__ g2,
                                                    const float* __restrict__ v3,
                                                    const float* __restrict__ g3)
{
    int blk = blockIdx.x;
    const float *v, *g;
    float* wt;
    int bx, by, OSTRIDE, NOV;
    if (blk < 64) { v = v2; g = g2; wt = d_WT2; bx = blk & 7; by = blk >> 3; OSTRIDE = 512; NOV = 512; }
    else { int l = blk - 64; v = v3; g = g3; wt = d_WT3; bx = l & 7; by = l >> 3; OSTRIDE = 128; NOV = 100; }
    constexpr int NI = 512;
    int i0 = bx * 64, o0 = by * 64;

    __shared__ float sscale[64];
    __shared__ float tile[64][65];
    int tid = threadIdx.x, lane = tid & 31, w = tid >> 5;

    #pragma unroll
    for (int r = 0; r < 8; r++) {
        int o = o0 + w * 8 + r;
        float s = 0.f;
        if (o < NOV) {
            const float* row = v + (size_t)o * NI;
            #pragma unroll
            for (int k = 0; k < 16; k++) { float x = row[lane + 32 * k]; s = fmaf(x, x, s); }
        }
        #pragma unroll
        for (int d = 16; d > 0; d >>= 1) s += __shfl_down_sync(0xffffffffu, s, d);
        if (lane == 0) sscale[w * 8 + r] = (o < NOV) ? g[o] / sqrtf(s) : 0.f;
    }
    __syncthreads();

    int oy = tid >> 4;
    int ix = (tid & 15) * 4;
    #pragma unroll
    for (int k = 0; k < 4; k++) {
        int ol = oy + k * 16;
        int o  = o0 + ol;
        float4 val = make_float4(0.f, 0.f, 0.f, 0.f);
        if (o < NOV) val = *(const float4*)&v[(size_t)o * NI + i0 + ix];
        tile[ix + 0][ol] = val.x;
        tile[ix + 1][ol] = val.y;
        tile[ix + 2][ol] = val.z;
        tile[ix + 3][ol] = val.w;
    }
    __syncthreads();

    int iy = tid >> 4;
    int ox = (tid & 15) * 4;
    float4 sc;
    sc.x = sscale[ox + 0]; sc.y = sscale[ox + 1];
    sc.z = sscale[ox + 2]; sc.w = sscale[ox + 3];
    #pragma unroll
    for (int k = 0; k < 4; k++) {
        int il = iy + k * 16;
        float4 w4;
        w4.x = tile[il][ox + 0] * sc.x;
        w4.y = tile[il][ox + 1] * sc.y;
        w4.z = tile[il][ox + 2] * sc.z;
        w4.w = tile[il][ox + 3] * sc.w;
        *(float4*)&wt[(size_t)(i0 + il) * OSTRIDE + o0 + ox] = w4;
    }
}

// ---------------- layer-1 sparse gather, i-halved, float4 x 128 ----------------
__global__ __launch_bounds__(128) void gather_hid1()
{
    const float4* __restrict__ wt = (const float4*)d_WT1;
    int t = blockIdx.x, b = blockIdx.y, h = blockIdx.z;
    const unsigned* bp = d_bits0 + ((size_t)t * B + b) * NW0 + h * HW;

    __shared__ unsigned short sidx[HW * 32];
    __shared__ int wcnt[4];
    int tid = threadIdx.x, lane = tid & 31, w = tid >> 5;

    int word = w * 32 + lane;
    unsigned m = bp[word];
    int c = __popc(m);
    int x = c;
    #pragma unroll
    for (int d = 1; d < 32; d <<= 1) {
        int y = __shfl_up_sync(0xffffffffu, x, d);
        if (lane >= d) x += y;
    }
    if (lane == 31) wcnt[w] = x;
    __syncthreads();
    int base = 0;
    #pragma unroll
    for (int j = 0; j < 4; j++) if (j < w) base += wcnt[j];
    int mybase = base + x - c;
    while (m) {
        int bpos = __ffs((int)m) - 1;
        m &= m - 1;
        sidx[mybase++] = (unsigned short)(word * 32 + bpos);
    }
    __syncthreads();

    int cnt = wcnt[0] + wcnt[1] + wcnt[2] + wcnt[3];
    int rowbase = h * (CIN / 2);

    float ax = 0.f, ay = 0.f, az = 0.f, aw = 0.f;
    int k = 0;
    for (; k + 8 <= cnt; k += 8) {
        float4 r[8];
        #pragma unroll
        for (int u = 0; u < 8; u++) {
            int i = rowbase + sidx[k + u];
            r[u] = wt[(size_t)i * 128 + tid];
        }
        #pragma unroll
        for (int u = 0; u < 8; u++) { ax += r[u].x; ay += r[u].y; az += r[u].z; aw += r[u].w; }
    }
    for (; k < cnt; k++) {
        int i = rowbase + sidx[k];
        float4 r0 = wt[(size_t)i * 128 + tid];
        ax += r0.x; ay += r0.y; az += r0.z; aw += r0.w;
    }
    float4 o; o.x = ax; o.y = ay; o.z = az; o.w = aw;
    ((float4*)d_zpart[h])[((size_t)t * B + b) * 128 + tid] = o;
}

// ---------------- LIF layer 1: sums the 2 half-partials, depth-8 prefetch ------
__global__ void lif_hid1(const float* __restrict__ cds, const float* __restrict__ vds)
{
    int gid  = blockIdx.x * blockDim.x + threadIdx.x;  // b*512+o
    int lane = threadIdx.x & 31;
    float a  = 1.f - cds[0];
    float bb = 1.f - vds[0];
    float cur = 0.f, volt = 0.f;

    float2 zb[8];
    #pragma unroll
    for (int j = 0; j < 8; j++) {
        zb[j].x = d_zpart[0][(size_t)j * (B * CHID) + gid];
        zb[j].y = d_zpart[1][(size_t)j * (B * CHID) + gid];
    }

    #pragma unroll 8
    for (int t = 0; t < T; t++) {
        float2 p = zb[t & 7];
        float zt = p.x + p.y;
        int tp = t + 8;
        if (tp < T) {
            zb[t & 7].x = d_zpart[0][(size_t)tp * (B * CHID) + gid];
            zb[t & 7].y = d_zpart[1][(size_t)tp * (B * CHID) + gid];
        }
        cur  = fmaf(a, cur, zt);
        volt = fmaf(bb, volt, cur);
        bool s = volt >= THRESH;
        unsigned msk = __ballot_sync(0xffffffffu, s);
        volt = s ? 0.f : volt;
        if (lane == 0) d_bits1[(size_t)t * (B * NW1) + (gid >> 5)] = msk;
    }
}

// ---------------- layer-2 t-grouped gather: block = (t-group of G, b) -----------
// warp 0 builds ascending (row, tmask) list from the union of G masks;
// main loop: 4 independent row loads then warp-uniform adds into acc[G].
// per-t accumulation order = ascending row = identical to the per-t kernel.
__global__ __launch_bounds__(128) void gather_hid2g()
{
    const float4* __restrict__ wt = (const float4*)d_WT2;
    int tg = blockIdx.x, b = blockIdx.y;
    int t0 = tg * G;

    __shared__ ushort2 slist[CHID];
    __shared__ int scount;
    __shared__ unsigned smask[G][NW1];
    int tid = threadIdx.x;

    // FIX R10: G*NW1 = 160 > blockDim 128 -> strided load
    for (int idx = tid; idx < G * NW1; idx += 128) {
        int tt = idx / NW1, w = idx % NW1;
        smask[tt][w] = d_bits1[(size_t)(t0 + tt) * (B * NW1) + b * NW1 + w];
    }
    __syncthreads();

    if (tid < 32) {
        int w = tid;
        unsigned u = 0;
        unsigned m[G];
        if (w < NW1) {
            #pragma unroll
            for (int j = 0; j < G; j++) { m[j] = smask[j][w]; u |= m[j]; }
        }
        int c = __popc(u);
        int x = c;
        #pragma unroll
        for (int d = 1; d < 32; d <<= 1) {
            int y = __shfl_up_sync(0xffffffffu, x, d);
            if (tid >= d) x += y;
        }
        if (tid == 31) scount = x;
        int base = x - c;
        while (u) {
            int bpos = __ffs((int)u) - 1;
            u &= u - 1;
            unsigned tm = 0;
            #pragma unroll
            for (int j = 0; j < G; j++) tm |= ((m[j] >> bpos) & 1u) << j;
            slist[base++] = make_ushort2((unsigned short)(w * 32 + bpos), (unsigned short)tm);
        }
    }
    __syncthreads();

    int cnt = scount;
    float4 acc[G];
    #pragma unroll
    for (int j = 0; j < G; j++) acc[j] = make_float4(0.f, 0.f, 0.f, 0.f);

    #define ADD_ROW(E, W)                                                          \
        { unsigned _tm = (E).y;                                                    \
          _Pragma("unroll")                                                        \
          for (int j = 0; j < G; j++)                                              \
              if (_tm & (1u << j)) {                                               \
                  acc[j].x += (W).x; acc[j].y += (W).y;                            \
                  acc[j].z += (W).z; acc[j].w += (W).w;                            \
              } }

    int k = 0;
    for (; k + 4 <= cnt; k += 4) {
        ushort2 e0 = slist[k + 0], e1 = slist[k + 1], e2 = slist[k + 2], e3 = slist[k + 3];
        float4 w0 = wt[(size_t)e0.x * 128 + tid];
        float4 w1 = wt[(size_t)e1.x * 128 + tid];
        float4 w2 = wt[(size_t)e2.x * 128 + tid];
        float4 w3 = wt[(size_t)e3.x * 128 + tid];
        ADD_ROW(e0, w0); ADD_ROW(e1, w1); ADD_ROW(e2, w2); ADD_ROW(e3, w3);
    }
    for (; k < cnt; k++) {
        ushort2 e = slist[k];
        float4 w4 = wt[(size_t)e.x * 128 + tid];
        ADD_ROW(e, w4);
    }
    #undef ADD_ROW

    #pragma unroll
    for (int j = 0; j < G; j++)
        ((float4*)d_z)[((size_t)(t0 + j) * B + b) * 128 + tid] = acc[j];
}

// ---------------- layer-3 t-grouped gather ---------------------------------------
__global__ __launch_bounds__(128) void gather_out_g()
{
    int tg = blockIdx.x, b = blockIdx.y;
    int t0 = tg * G;

    __shared__ ushort2 slist[CHID];
    __shared__ int scount;
    __shared__ unsigned smask[G][NW1];
    int tid = threadIdx.x;

    // FIX R10: strided load for 160 words with 128 threads
    for (int idx = tid; idx < G * NW1; idx += 128) {
        int tt = idx / NW1, w = idx % NW1;
        smask[tt][w] = d_bits2[(size_t)(t0 + tt) * (B * NW1) + b * NW1 + w];
    }
    __syncthreads();

    if (tid < 32) {
        int w = tid;
        unsigned u = 0;
        unsigned m[G];
        if (w < NW1) {
            #pragma unroll
            for (int j = 0; j < G; j++) { m[j] = smask[j][w]; u |= m[j]; }
        }
        int c = __popc(u);
        int x = c;
        #pragma unroll
        for (int d = 1; d < 32; d <<= 1) {
            int y = __shfl_up_sync(0xffffffffu, x, d);
            if (tid >= d) x += y;
        }
        if (tid == 31) scount = x;
        int base = x - c;
        while (u) {
            int bpos = __ffs((int)u) - 1;
            u &= u - 1;
            unsigned tm = 0;
            #pragma unroll
            for (int j = 0; j < G; j++) tm |= ((m[j] >> bpos) & 1u) << j;
            slist[base++] = make_ushort2((unsigned short)(w * 32 + bpos), (unsigned short)tm);
        }
    }
    __syncthreads();

    int cnt = scount;
    float acc[G];
    #pragma unroll
    for (int j = 0; j < G; j++) acc[j] = 0.f;

    #define ADD_ROW1(E, W)                                                         \
        { unsigned _tm = (E).y;                                                    \
          _Pragma("unroll")                                                        \
          for (int j = 0; j < G; j++)                                              \
              if (_tm & (1u << j)) acc[j] += (W); }

    int k = 0;
    for (; k + 4 <= cnt; k += 4) {
        ushort2 e0 = slist[k + 0], e1 = slist[k + 1], e2 = slist[k + 2], e3 = slist[k + 3];
        float w0 = d_WT3[(size_t)e0.x * 128 + tid];
        float w1 = d_WT3[(size_t)e1.x * 128 + tid];
        float w2 = d_WT3[(size_t)e2.x * 128 + tid];
        float w3 = d_WT3[(size_t)e3.x * 128 + tid];
        ADD_ROW1(e0, w0); ADD_ROW1(e1, w1); ADD_ROW1(e2, w2); ADD_ROW1(e3, w3);
    }
    for (; k < cnt; k++) {
        ushort2 e = slist[k];
        float w4 = d_WT3[(size_t)e.x * 128 + tid];
        ADD_ROW1(e, w4);
    }
    #undef ADD_ROW1

    if (tid < COUT) {
        #pragma unroll
        for (int j = 0; j < G; j++)
            d_z3[((size_t)(t0 + j) * B + b) * COUT + tid] = acc[j];
    }
}

// ---------------- LIF layer 2 (reads d_z), depth-8 prefetch --------------------
__global__ void lif_hid2(const float* __restrict__ cds, const float* __restrict__ vds)
{
    int gid  = blockIdx.x * blockDim.x + threadIdx.x;
    int lane = threadIdx.x & 31;
    float a  = 1.f - cds[1];
    float bb = 1.f - vds[1];
    float cur = 0.f, volt = 0.f;

    float zbuf[8];
    #pragma unroll
    for (int j = 0; j < 8; j++) zbuf[j] = d_z[(size_t)j * (B * CHID) + gid];

    #pragma unroll 8
    for (int t = 0; t < T; t++) {
        float zt = zbuf[t & 7];
        int tp = t + 8;
        if (tp < T) zbuf[t & 7] = d_z[(size_t)tp * (B * CHID) + gid];
        cur  = fmaf(a, cur, zt);
        volt = fmaf(bb, volt, cur);
        bool s = volt >= THRESH;
        unsigned msk = __ballot_sync(0xffffffffu, s);
        volt = s ? 0.f : volt;
        if (lane == 0) d_bits2[(size_t)t * (B * NW1) + (gid >> 5)] = msk;
    }
}

// ---------------- LIF output layer -> d_out [b][c][t] float --------------------
__global__ void lif_out(const float* __restrict__ cds, const float* __restrict__ vds,
                        float* __restrict__ out)
{
    int gid = blockIdx.x * blockDim.x + threadIdx.x;
    if (gid >= B * COUT) return;
    int b = gid / COUT, c = gid % COUT;
    float a  = 1.f - cds[2];
    float bb = 1.f - vds[2];
    float cur = 0.f, volt = 0.f;
    float* orow = out + ((size_t)b * COUT + c) * T;

    float zbuf[8];
    #pragma unroll
    for (int j = 0; j < 8; j++) zbuf[j] = d_z3[(size_t)j * (B * COUT) + gid];

    #pragma unroll 8
    for (int t = 0; t < T; t++) {
        float zt = zbuf[t & 7];
        int tp = t + 8;
        if (tp < T) zbuf[t & 7] = d_z3[(size_t)tp * (B * COUT) + gid];
        cur  = fmaf(a, cur, zt);
        volt = fmaf(bb, volt, cur);
        bool s = volt >= THRESH;
        volt = s ? 0.f : volt;
        orow[t] = s ? 1.0f : 0.0f;
    }
}

// ---------------- streams/events (context resources, not tracked device mem) ---
struct SideStreams {
    cudaStream_t s1, s2;
    cudaEvent_t  evRoot, evBits, evPrep;
    SideStreams() {
        cudaStreamCreateWithFlags(&s1, cudaStreamNonBlocking);
        cudaStreamCreateWithFlags(&s2, cudaStreamNonBlocking);
        cudaEventCreateWithFlags(&evRoot, cudaEventDisableTiming);
        cudaEventCreateWithFlags(&evBits, cudaEventDisableTiming);
        cudaEventCreateWithFlags(&evPrep, cudaEventDisableTiming);
    }
};
static SideStreams g_ss;

// ---------------- launch ---------------------------------------------------------
extern "C" void kernel_launch(void* const* d_in, const int* in_sizes, int n_in,
                              void* d_out, int out_size)
{
    const float* spike = (const float*)d_in[0];
    const float* v1 = (const float*)d_in[1];
    const float* g1 = (const float*)d_in[2];
    const float* v2 = (const float*)d_in[3];
    const float* g2 = (const float*)d_in[4];
    const float* v3 = (const float*)d_in[5];
    const float* g3 = (const float*)d_in[6];
    const float* cds = (const float*)d_in[7];
    const float* vds = (const float*)d_in[8];
    float* out = (float*)d_out;

    // fork
    cudaEventRecord(g_ss.evRoot, 0);
    cudaStreamWaitEvent(g_ss.s1, g_ss.evRoot, 0);
    cudaStreamWaitEvent(g_ss.s2, g_ss.evRoot, 0);

    // #1: layers 2+3 full weight prep (s2)
    fused_prep23<<<80, 256, 0, g_ss.s2>>>(v2, g2, v3, g3);
    cudaEventRecord(g_ss.evPrep, g_ss.s2);

    // #2: bitpack + layer-1 norms (s1)
    bitpack_norm0<<<4096 + CHID, 256, 0, g_ss.s1>>>(spike, v1, g1);
    cudaEventRecord(g_ss.evBits, g_ss.s1);

    // main chain
    cudaStreamWaitEvent(0, g_ss.evBits, 0);
    wnorm_t0<<<dim3(CIN / 64, CHID / 64), 256>>>(v1);        // #3
    gather_hid1<<<dim3(T, B, 2), 128>>>();                   // #4 (profiled)
    lif_hid1<<<(B * CHID) / 128, 128>>>(cds, vds);           // #5
    cudaStreamWaitEvent(0, g_ss.evPrep, 0);
    gather_hid2g<<<dim3(NTG, B), 128>>>();                   // #6
    lif_hid2<<<(B * CHID) / 128, 128>>>(cds, vds);           // #7
    gather_out_g<<<dim3(NTG, B), 128>>>();                   // #8
    lif_out<<<(B * COUT + 127) / 128, 128>>>(cds, vds, out); // #9
}

// round 12
// speedup vs baseline: 1.1408x; 1.1408x over previous
#include <cuda_runtime.h>
#include <cstdint>

#define THRESH 1.25f

constexpr int B    = 16;
constexpr int CIN  = 8192;   // 64*64*2
constexpr int CHID = 512;
constexpr int COUT = 100;
constexpr int T    = 300;
constexpr int NW0  = CIN / 32;   // 256 words per (b,t)
constexpr int NW1  = CHID / 32;  // 16 words per (b,t)
constexpr int HW   = NW0 / 2;    // 128 words per half

// ---------------- scratch (static device globals; allocation-free) -------------
__device__ __align__(256) float    d_WT1[CIN * CHID];     // 16 MB  [i][o]
__device__ __align__(256) float    d_WT2[CHID * CHID];    // 1 MB   [i][o]
__device__ __align__(256) float    d_WT3[CHID * 128];     // 256 KB [i][o pad 128]
__device__ __align__(256) float    d_scale1[CHID];
__device__ __align__(256) unsigned d_bits0[T * B * NW0];  // input spikes [t][b][w]
__device__ __align__(256) unsigned d_bits1[T * B * NW1];  // hidden spikes [t][b][w]
__device__ __align__(256) unsigned d_bits2[T * B * NW1];
__device__ __align__(256) float    d_zpart[2][T * B * CHID]; // layer-1 i-half partials
__device__ __align__(256) float    d_z [T * B * CHID];    // layer-2 z [t][b][o]
__device__ __align__(256) float    d_z3[T * B * COUT];

// ---------------- prep_all: layer-2/3 norms+transpose AND layer-1 norms --------
// blocks 0..63: layer2 tiles; 64..79: layer3 tiles; 80..591: layer-1 row norms
__global__ __launch_bounds__(256) void prep_all(const float* __restrict__ v1,
                                                const float* __restrict__ g1,
                                                const float* __restrict__ v2,
                                                const float* __restrict__ g2,
                                                const float* __restrict__ v3,
                                                const float* __restrict__ g3)
{
    int blk = blockIdx.x;
    int tid = threadIdx.x, lane = tid & 31, w = tid >> 5;

    if (blk >= 80) {
        // layer-1 row norm, identical reduction order to original row_norm<0>
        __shared__ float red[8];
        int r = blk - 80;   // 0..511
        const float* row = v1 + (size_t)r * CIN;
        float s = 0.f;
        for (int i = tid; i < CIN; i += 256) { float x = row[i]; s = fmaf(x, x, s); }
        #pragma unroll
        for (int d = 16; d > 0; d >>= 1) s += __shfl_down_sync(0xffffffffu, s, d);
        if (lane == 0) red[w] = s;
        __syncthreads();
        if (tid == 0) {
            float tot = 0.f;
            #pragma unroll
            for (int j = 0; j < 8; j++) tot += red[j];
            d_scale1[r] = g1[r] / sqrtf(tot);
        }
        return;
    }

    const float *v, *g;
    float* wt;
    int bx, by, OSTRIDE, NOV;
    if (blk < 64) { v = v2; g = g2; wt = d_WT2; bx = blk & 7; by = blk >> 3; OSTRIDE = 512; NOV = 512; }
    else { int l = blk - 64; v = v3; g = g3; wt = d_WT3; bx = l & 7; by = l >> 3; OSTRIDE = 128; NOV = 100; }
    constexpr int NI = 512;
    int i0 = bx * 64, o0 = by * 64;

    __shared__ float sscale[64];
    __shared__ float tile[64][65];

    #pragma unroll
    for (int r = 0; r < 8; r++) {
        int o = o0 + w * 8 + r;
        float s = 0.f;
        if (o < NOV) {
            const float* row = v + (size_t)o * NI;
            #pragma unroll
            for (int k = 0; k < 16; k++) { float x = row[lane + 32 * k]; s = fmaf(x, x, s); }
        }
        #pragma unroll
        for (int d = 16; d > 0; d >>= 1) s += __shfl_down_sync(0xffffffffu, s, d);
        if (lane == 0) sscale[w * 8 + r] = (o < NOV) ? g[o] / sqrtf(s) : 0.f;
    }
    __syncthreads();

    int oy = tid >> 4;
    int ix = (tid & 15) * 4;
    #pragma unroll
    for (int k = 0; k < 4; k++) {
        int ol = oy + k * 16;
        int o  = o0 + ol;
        float4 val = make_float4(0.f, 0.f, 0.f, 0.f);
        if (o < NOV) val = *(const float4*)&v[(size_t)o * NI + i0 + ix];
        tile[ix + 0][ol] = val.x;
        tile[ix + 1][ol] = val.y;
        tile[ix + 2][ol] = val.z;
        tile[ix + 3][ol] = val.w;
    }
    __syncthreads();

    int iy = tid >> 4;
    int ox = (tid & 15) * 4;
    float4 sc;
    sc.x = sscale[ox + 0]; sc.y = sscale[ox + 1];
    sc.z = sscale[ox + 2]; sc.w = sscale[ox + 3];
    #pragma unroll
    for (int k = 0; k < 4; k++) {
        int il = iy + k * 16;
        float4 w4;
        w4.x = tile[il][ox + 0] * sc.x;
        w4.y = tile[il][ox + 1] * sc.y;
        w4.z = tile[il][ox + 2] * sc.z;
        w4.w = tile[il][ox + 3] * sc.w;
        *(float4*)&wt[(size_t)(i0 + il) * OSTRIDE + o0 + ox] = w4;
    }
}

// ---------------- bitpack only (coalesced, smem byte-transpose) ----------------
__global__ __launch_bounds__(256) void bitpack(const float* __restrict__ spike)
{
    __shared__ unsigned char sb[32 * 308];
    int blk = blockIdx.x;
    int b  = blk >> 8;
    int ig = blk & 255;
    int tid = threadIdx.x, lane = tid & 31, w = tid >> 5;

    #pragma unroll
    for (int k = 0; k < 4; k++) {
        int il = w + 8 * k;
        const float4* row4 = (const float4*)(spike + ((size_t)b * CIN + ig * 32 + il) * T);
        #pragma unroll
        for (int j = 0; j < 3; j++) {
            int f = lane + 32 * j;
            if (f < 75) {
                float4 v = row4[f];
                unsigned p = (v.x > 0.5f ? 1u : 0u)
                           | (v.y > 0.5f ? 1u : 0u) << 8
                           | (v.z > 0.5f ? 1u : 0u) << 16
                           | (v.w > 0.5f ? 1u : 0u) << 24;
                *(unsigned*)&sb[il * 308 + 4 * f] = p;
            }
        }
    }
    __syncthreads();
    for (int t = tid; t < T; t += 256) {
        unsigned m = 0;
        #pragma unroll
        for (int i = 0; i < 32; i++) m |= (unsigned)sb[i * 308 + t] << i;
        d_bits0[(size_t)t * (B * NW0) + b * NW0 + ig] = m;
    }
}

// ---------------- layer-1 transpose + scale: WT1[i][o] = v1[o][i]*scale1[o] ----
__global__ void wnorm_t0(const float* __restrict__ v)
{
    __shared__ float tile[64][65];
    int i0 = blockIdx.x * 64, o0 = blockIdx.y * 64;
    int tid = threadIdx.x;
    int oy = tid >> 4;
    int ix = (tid & 15) * 4;

    #pragma unroll
    for (int k = 0; k < 4; k++) {
        int ol = oy + k * 16;
        float4 val = *(const float4*)&v[(size_t)(o0 + ol) * CIN + i0 + ix];
        tile[ix + 0][ol] = val.x;
        tile[ix + 1][ol] = val.y;
        tile[ix + 2][ol] = val.z;
        tile[ix + 3][ol] = val.w;
    }
    __syncthreads();

    int iy = tid >> 4;
    int ox = (tid & 15) * 4;
    float4 sc = *(const float4*)&d_scale1[o0 + ox];
    #pragma unroll
    for (int k = 0; k < 4; k++) {
        int il = iy + k * 16;
        float4 w;
        w.x = tile[il][ox + 0] * sc.x;
        w.y = tile[il][ox + 1] * sc.y;
        w.z = tile[il][ox + 2] * sc.z;
        w.w = tile[il][ox + 3] * sc.w;
        *(float4*)&d_WT1[(size_t)(i0 + il) * CHID + o0 + ox] = w;
    }
}

// ---------------- layer-1 sparse gather, i-halved, float4 x 128 ----------------
__global__ __launch_bounds__(128) void gather_hid1()
{
    const float4* __restrict__ wt = (const float4*)d_WT1;
    int t = blockIdx.x, b = blockIdx.y, h = blockIdx.z;
    const unsigned* bp = d_bits0 + ((size_t)t * B + b) * NW0 + h * HW;

    __shared__ unsigned short sidx[HW * 32];
    __shared__ int wcnt[4];
    int tid = threadIdx.x, lane = tid & 31, w = tid >> 5;

    int word = w * 32 + lane;
    unsigned m = bp[word];
    int c = __popc(m);
    int x = c;
    #pragma unroll
    for (int d = 1; d < 32; d <<= 1) {
        int y = __shfl_up_sync(0xffffffffu, x, d);
        if (lane >= d) x += y;
    }
    if (lane == 31) wcnt[w] = x;
    __syncthreads();
    int base = 0;
    #pragma unroll
    for (int j = 0; j < 4; j++) if (j < w) base += wcnt[j];
    int mybase = base + x - c;
    while (m) {
        int bpos = __ffs((int)m) - 1;
        m &= m - 1;
        sidx[mybase++] = (unsigned short)(word * 32 + bpos);
    }
    __syncthreads();

    int cnt = wcnt[0] + wcnt[1] + wcnt[2] + wcnt[3];
    int rowbase = h * (CIN / 2);

    float ax = 0.f, ay = 0.f, az = 0.f, aw = 0.f;
    int k = 0;
    for (; k + 8 <= cnt; k += 8) {
        float4 r[8];
        #pragma unroll
        for (int u = 0; u < 8; u++) {
            int i = rowbase + sidx[k + u];
            r[u] = wt[(size_t)i * 128 + tid];
        }
        #pragma unroll
        for (int u = 0; u < 8; u++) { ax += r[u].x; ay += r[u].y; az += r[u].z; aw += r[u].w; }
    }
    for (; k < cnt; k++) {
        int i = rowbase + sidx[k];
        float4 r0 = wt[(size_t)i * 128 + tid];
        ax += r0.x; ay += r0.y; az += r0.z; aw += r0.w;
    }
    float4 o; o.x = ax; o.y = ay; o.z = az; o.w = aw;
    ((float4*)d_zpart[h])[((size_t)t * B + b) * 128 + tid] = o;
}

// ---------------- LIF layer 1: sums the 2 half-partials, depth-8 prefetch ------
__global__ void lif_hid1(const float* __restrict__ cds, const float* __restrict__ vds)
{
    int gid  = blockIdx.x * blockDim.x + threadIdx.x;  // b*512+o
    int lane = threadIdx.x & 31;
    float a  = 1.f - cds[0];
    float bb = 1.f - vds[0];
    float cur = 0.f, volt = 0.f;

    float2 zb[8];
    #pragma unroll
    for (int j = 0; j < 8; j++) {
        zb[j].x = d_zpart[0][(size_t)j * (B * CHID) + gid];
        zb[j].y = d_zpart[1][(size_t)j * (B * CHID) + gid];
    }

    #pragma unroll 8
    for (int t = 0; t < T; t++) {
        float2 p = zb[t & 7];
        float zt = p.x + p.y;
        int tp = t + 8;
        if (tp < T) {
            zb[t & 7].x = d_zpart[0][(size_t)tp * (B * CHID) + gid];
            zb[t & 7].y = d_zpart[1][(size_t)tp * (B * CHID) + gid];
        }
        cur  = fmaf(a, cur, zt);
        volt = fmaf(bb, volt, cur);
        bool s = volt >= THRESH;
        unsigned msk = __ballot_sync(0xffffffffu, s);
        volt = s ? 0.f : volt;
        if (lane == 0) d_bits1[(size_t)t * (B * NW1) + (gid >> 5)] = msk;
    }
}

// ---------------- layer-2 sparse gather, per-t, float4 x 128 (R9 version) ------
__global__ __launch_bounds__(128) void gather_hid2()
{
    const float4* __restrict__ wt = (const float4*)d_WT2;
    int t = blockIdx.x, b = blockIdx.y;
    const unsigned* bp = d_bits1 + ((size_t)t * B + b) * NW1;

    __shared__ unsigned short sidx[NW1 * 32];
    __shared__ int scount;
    int tid = threadIdx.x, lane = tid & 31;

    if (tid < 32) {
        unsigned m = (lane < NW1) ? bp[lane] : 0u;
        int c = __popc(m);
        int x = c;
        #pragma unroll
        for (int d = 1; d < 32; d <<= 1) {
            int y = __shfl_up_sync(0xffffffffu, x, d);
            if (lane >= d) x += y;
        }
        int base = x - c;
        while (m) {
            int bpos = __ffs((int)m) - 1;
            m &= m - 1;
            sidx[base++] = (unsigned short)(lane * 32 + bpos);
        }
        if (lane == 31) scount = x;
    }
    __syncthreads();

    int cnt = scount;
    float ax = 0.f, ay = 0.f, az = 0.f, aw = 0.f;
    int k = 0;
    for (; k + 8 <= cnt; k += 8) {
        float4 r[8];
        #pragma unroll
        for (int u = 0; u < 8; u++) { int i = sidx[k + u]; r[u] = wt[(size_t)i * 128 + tid]; }
        #pragma unroll
        for (int u = 0; u < 8; u++) { ax += r[u].x; ay += r[u].y; az += r[u].z; aw += r[u].w; }
    }
    for (; k < cnt; k++) {
        float4 r0 = wt[(size_t)sidx[k] * 128 + tid];
        ax += r0.x; ay += r0.y; az += r0.z; aw += r0.w;
    }
    float4 o; o.x = ax; o.y = ay; o.z = az; o.w = aw;
    ((float4*)d_z)[((size_t)t * B + b) * 128 + tid] = o;
}

// ---------------- layer-3 per-t gather (R9 version) ------------------------------
__global__ void gather_out()
{
    int t = blockIdx.x, b = blockIdx.y;
    const unsigned* bp = d_bits2 + ((size_t)t * B + b) * NW1;

    __shared__ unsigned short sidx[NW1 * 32];
    __shared__ int scount;
    int tid = threadIdx.x, lane = tid & 31;

    if (tid < 32) {
        unsigned m = (lane < NW1) ? bp[lane] : 0u;
        int c = __popc(m);
        int x = c;
        #pragma unroll
        for (int d = 1; d < 32; d <<= 1) {
            int y = __shfl_up_sync(0xffffffffu, x, d);
            if (lane >= d) x += y;
        }
        int base = x - c;
        while (m) {
            int bpos = __ffs((int)m) - 1;
            m &= m - 1;
            sidx[base++] = (unsigned short)(lane * 32 + bpos);
        }
        if (lane == 31) scount = x;
    }
    __syncthreads();

    int cnt = scount;
    float acc = 0.f;
    int k = 0;
    for (; k + 8 <= cnt; k += 8) {
        float r[8];
        #pragma unroll
        for (int u = 0; u < 8; u++) { int i = sidx[k + u]; r[u] = d_WT3[i * 128 + tid]; }
        #pragma unroll
        for (int u = 0; u < 8; u++) acc += r[u];
    }
    for (; k < cnt; k++) acc += d_WT3[sidx[k] * 128 + tid];

    if (tid < COUT) d_z3[((size_t)t * B + b) * COUT + tid] = acc;
}

// ---------------- LIF layer 2 (reads d_z), depth-8 prefetch --------------------
__global__ void lif_hid2(const float* __restrict__ cds, const float* __restrict__ vds)
{
    int gid  = blockIdx.x * blockDim.x + threadIdx.x;
    int lane = threadIdx.x & 31;
    float a  = 1.f - cds[1];
    float bb = 1.f - vds[1];
    float cur = 0.f, volt = 0.f;

    float zbuf[8];
    #pragma unroll
    for (int j = 0; j < 8; j++) zbuf[j] = d_z[(size_t)j * (B * CHID) + gid];

    #pragma unroll 8
    for (int t = 0; t < T; t++) {
        float zt = zbuf[t & 7];
        int tp = t + 8;
        if (tp < T) zbuf[t & 7] = d_z[(size_t)tp * (B * CHID) + gid];
        cur  = fmaf(a, cur, zt);
        volt = fmaf(bb, volt, cur);
        bool s = volt >= THRESH;
        unsigned msk = __ballot_sync(0xffffffffu, s);
        volt = s ? 0.f : volt;
        if (lane == 0) d_bits2[(size_t)t * (B * NW1) + (gid >> 5)] = msk;
    }
}

// ---------------- LIF output layer -> d_out [b][c][t] float --------------------
__global__ void lif_out(const float* __restrict__ cds, const float* __restrict__ vds,
                        float* __restrict__ out)
{
    int gid = blockIdx.x * blockDim.x + threadIdx.x;
    if (gid >= B * COUT) return;
    int b = gid / COUT, c = gid % COUT;
    float a  = 1.f - cds[2];
    float bb = 1.f - vds[2];
    float cur = 0.f, volt = 0.f;
    float* orow = out + ((size_t)b * COUT + c) * T;

    float zbuf[8];
    #pragma unroll
    for (int j = 0; j < 8; j++) zbuf[j] = d_z3[(size_t)j * (B * COUT) + gid];

    #pragma unroll 8
    for (int t = 0; t < T; t++) {
        float zt = zbuf[t & 7];
        int tp = t + 8;
        if (tp < T) zbuf[t & 7] = d_z3[(size_t)tp * (B * COUT) + gid];
        cur  = fmaf(a, cur, zt);
        volt = fmaf(bb, volt, cur);
        bool s = volt >= THRESH;
        volt = s ? 0.f : volt;
        orow[t] = s ? 1.0f : 0.0f;
    }
}

// ---------------- streams/events (context resources, not tracked device mem) ---
struct SideStreams {
    cudaStream_t s1, s2;
    cudaEvent_t  evRoot, evBits, evPrep;
    SideStreams() {
        cudaStreamCreateWithFlags(&s1, cudaStreamNonBlocking);
        cudaStreamCreateWithFlags(&s2, cudaStreamNonBlocking);
        cudaEventCreateWithFlags(&evRoot, cudaEventDisableTiming);
        cudaEventCreateWithFlags(&evBits, cudaEventDisableTiming);
        cudaEventCreateWithFlags(&evPrep, cudaEventDisableTiming);
    }
};
static SideStreams g_ss;

// ---------------- launch ---------------------------------------------------------
extern "C" void kernel_launch(void* const* d_in, const int* in_sizes, int n_in,
                              void* d_out, int out_size)
{
    const float* spike = (const float*)d_in[0];
    const float* v1 = (const float*)d_in[1];
    const float* g1 = (const float*)d_in[2];
    const float* v2 = (const float*)d_in[3];
    const float* g2 = (const float*)d_in[4];
    const float* v3 = (const float*)d_in[5];
    const float* g3 = (const float*)d_in[6];
    const float* cds = (const float*)d_in[7];
    const float* vds = (const float*)d_in[8];
    float* out = (float*)d_out;

    // fork
    cudaEventRecord(g_ss.evRoot, 0);
    cudaStreamWaitEvent(g_ss.s1, g_ss.evRoot, 0);
    cudaStreamWaitEvent(g_ss.s2, g_ss.evRoot, 0);

    // #1: ALL norms (incl. layer-1) + layer-2/3 transposes (s2, ~10 us)
    prep_all<<<592, 256, 0, g_ss.s2>>>(v1, g1, v2, g2, v3, g3);
    cudaEventRecord(g_ss.evPrep, g_ss.s2);

    // #2: pure bitpack (s1, ~25 us) — parallel with prep_all AND wt0
    bitpack<<<4096, 256, 0, g_ss.s1>>>(spike);
    cudaEventRecord(g_ss.evBits, g_ss.s1);

    // main chain
    cudaStreamWaitEvent(0, g_ss.evPrep, 0);
    wnorm_t0<<<dim3(CIN / 64, CHID / 64), 256>>>(v1);        // #3 (overlaps bitpack)
    cudaStreamWaitEvent(0, g_ss.evBits, 0);
    gather_hid1<<<dim3(T, B, 2), 128>>>();                   // #4 (profiled)
    lif_hid1<<<(B * CHID) / 128, 128>>>(cds, vds);           // #5
    gather_hid2<<<dim3(T, B), 128>>>();                      // #6
    lif_hid2<<<(B * CHID) / 128, 128>>>(cds, vds);           // #7
    gather_out<<<dim3(T, B), 128>>>();                       // #8
    lif_out<<<(B * COUT + 127) / 128, 128>>>(cds, vds, out); // #9
}